// round 13
// baseline (speedup 1.0000x reference)
#include <cuda_runtime.h>
#include <math.h>

#define NB   2
#define NHD  8
#define HD   32
#define CH   256
#define HI   40
#define WIM  40
#define HW   1600
#define WSZ  15
#define WS2  225
#define NEGV 1e8f
#define INV_T 0.17677669529663687f   // 1/sqrt(32)

#define OUT_ELEMS  (HW*NB*CH)            // 819200
#define ATTN_ELEMS (NB*NHD*HW*WS2)       // 5760000

// ---- scratch ----
__device__ float g_qp[NB*NHD*HW*HD];     // [n][h][q][d] unscaled
__device__ float g_kp[NB*NHD*HW*HD];     // [n][h][j][d] scaled by 1/T
__device__ float g_vp[NB*NHD*HW*HD];
__device__ float g_ctx[HW*NB*CH];        // [i][n][c]
__device__ float g_rel[NB*NHD*WS2*HW];   // [n][h][w][q]  rel logits
__device__ float g_pb[ATTN_ELEMS];       // fallback p storage

// ============================================================
// Kernel 1: fused QKV projection. 128x64 tile, 512 threads,
// 4x4 outputs/thread (16 warps/SM for latency hiding).
// ============================================================
__global__ void __launch_bounds__(512) proj_kernel(
    const float* __restrict__ q, const float* __restrict__ k, const float* __restrict__ v,
    const float* __restrict__ Wq, const float* __restrict__ bq,
    const float* __restrict__ Wk, const float* __restrict__ bk,
    const float* __restrict__ Wv, const float* __restrict__ bv)
{
    __shared__ __align__(16) float Ws[128 * 33];
    __shared__ __align__(16) float Bs[32][64];

    int z = blockIdx.z;
    int n = z & 1, t = z >> 1;
    const float* X; const float* W; const float* b; float* Y; float scale;
    if (t == 0)      { X = q; W = Wq; b = bq; Y = g_qp; scale = 1.0f;  }
    else if (t == 1) { X = k; W = Wk; b = bk; Y = g_kp; scale = INV_T; }
    else             { X = v; W = Wv; b = bv; Y = g_vp; scale = 1.0f;  }
    X += (size_t)n * CH * HW;

    int o0 = blockIdx.y * 128, p0 = blockIdx.x * 64;
    int tid = threadIdx.x;
    int tx = tid & 15, ty = tid >> 4;     // ty 0..31 -> 4 rows each

    float acc[4][4] = {};

    for (int k0 = 0; k0 < CH; k0 += 32) {
#pragma unroll
        for (int s = 0; s < 8; s++) {
            int idx = tid + s * 512;
            int row = idx >> 5, col = idx & 31;
            Ws[row * 33 + col] = W[(size_t)(o0 + row) * CH + k0 + col];
        }
#pragma unroll
        for (int s = 0; s < 4; s++) {
            int idx = tid + s * 512;
            int col = idx & 63, row = idx >> 6;
            Bs[row][col] = X[(size_t)(k0 + row) * HW + p0 + col];
        }
        __syncthreads();
#pragma unroll
        for (int cc = 0; cc < 32; cc++) {
            float4 b4 = *reinterpret_cast<const float4*>(&Bs[cc][tx * 4]);
            float bb[4] = {b4.x, b4.y, b4.z, b4.w};
            float aa[4];
#pragma unroll
            for (int i = 0; i < 4; i++) aa[i] = Ws[(ty * 4 + i) * 33 + cc];
#pragma unroll
            for (int i = 0; i < 4; i++)
#pragma unroll
                for (int j = 0; j < 4; j++)
                    acc[i][j] = fmaf(aa[i], bb[j], acc[i][j]);
        }
        __syncthreads();
    }

#pragma unroll
    for (int i = 0; i < 4; i++) {
        int o = o0 + ty * 4 + i;
        int h = o >> 5, d = o & 31;
        float bias = b[o];
#pragma unroll
        for (int j = 0; j < 4; j++) {
            int p = p0 + tx * 4 + j;
            float val = (acc[i][j] + bias) * scale;
            Y[((size_t)(n * NHD + h) * HW + p) * HD + d] = val;
        }
    }
}

// ============================================================
// Kernel 2: rel logits GEMM (unchanged).
// ============================================================
__global__ void __launch_bounds__(256) relgemm_kernel(
    const float* __restrict__ relw_g,   // [NHD][WS2][HD]
    const float* __restrict__ relb_g)   // [NHD][WS2]
{
    __shared__ __align__(16) float sW[WS2 * HD];   // [w][d]
    __shared__ float sb[WS2];

    int q0 = blockIdx.x * 64, h = blockIdx.y, n = blockIdx.z;
    int tid = threadIdx.x;
    int nh = n * NHD + h;

    {
        const float4* src = reinterpret_cast<const float4*>(relw_g + (size_t)h * WS2 * HD);
        float4* dst = reinterpret_cast<float4*>(sW);
        for (int i = tid; i < WS2 * HD / 4; i += 256) dst[i] = src[i];
        const float* bs = relb_g + (size_t)h * WS2;
        for (int i = tid; i < WS2; i += 256) sb[i] = bs[i];
    }
    __syncthreads();

    int qi = tid & 63, wg = tid >> 6;
    int qq = q0 + qi;
    float4 qv[8];
    {
        const float4* qsrc = reinterpret_cast<const float4*>(
            g_qp + (size_t)(nh * HW + qq) * HD);
#pragma unroll
        for (int u = 0; u < 8; u++) qv[u] = qsrc[u];
    }
    float* dst = g_rel + (size_t)nh * WS2 * HW + qq;
#pragma unroll 1
    for (int w = wg; w < WS2; w += 4) {
        const float4* r4 = reinterpret_cast<const float4*>(sW + w * HD);
        float4 a = make_float4(0.f, 0.f, 0.f, 0.f);
#pragma unroll
        for (int u = 0; u < 8; u++) {
            float4 rv = r4[u], qu = qv[u];
            a.x = fmaf(qu.x, rv.x, a.x);
            a.y = fmaf(qu.y, rv.y, a.y);
            a.z = fmaf(qu.z, rv.z, a.z);
            a.w = fmaf(qu.w, rv.w, a.w);
        }
        dst[(size_t)w * HW] = (a.x + a.y) + (a.z + a.w) + sb[w];
    }
}

// ============================================================
// Kernel 3: local attention (unchanged from R12).
// ============================================================
#define GQ    2
#define QG    80
#define KROWS 16
#define PADW  54
#define KP    36
#define LPQ   240
#define SM_K      0                          // 16*54*36 = 31104
#define SM_L      31104                      // 80*240   = 19200
#define SM_V      50304                      // 226*32   = 7232
#define SM_FLOATS 57536
#define SM_BYTES  (SM_FLOATS * 4)            // 230144 B

__global__ void __launch_bounds__(640, 1) attn_kernel(
    const float* __restrict__ relv_g,   // [NHD][HD][WS2]
    float* __restrict__ p_out)
{
    int qy0 = blockIdx.x * GQ, h = blockIdx.y, n = blockIdx.z;
    int tid = threadIdx.x;
    extern __shared__ __align__(16) float sm[];
    float* sK = sm + SM_K;
    float* sL = sm + SM_L;
    float* sV = sm + SM_V;

    int nh = n * NHD + h;
    int nh_base = nh * HW;
    const float4 z4 = make_float4(0.f, 0.f, 0.f, 0.f);

    // ---- stage K (16 rows, OOB rows -> 0) + pad cols ----
    for (int i = tid; i < KROWS * 320; i += 640) {
        int r = i / 320, rem = i - r * 320;
        int ky = qy0 - 7 + r;
        float4 val = z4;
        if ((unsigned)ky < HI)
            val = reinterpret_cast<const float4*>(
                      g_kp + (size_t)(nh_base + ky * WIM) * HD)[rem];
        int kx = rem >> 3, u = rem & 7;
        *reinterpret_cast<float4*>(sK + (r * PADW + 7 + kx) * KP + 4 * u) = val;
    }
    for (int i = tid; i < KROWS * 112; i += 640) {
        int r = i / 112, rem = i - r * 112;
        int c = rem >> 3, u = rem & 7;
        int col = (c < 7) ? c : (c + 40);             // pads: 0..6, 47..53
        *reinterpret_cast<float4*>(sK + (r * PADW + col) * KP + 4 * u) = z4;
    }
    __syncthreads();

    // ---- logits: thread = (qg = tid%80, wg = tid/80 in 0..7) ----
    {
        int qg = tid % QG;
        int wg = tid / QG;
        int qyl = (qg >= 40) ? 1 : 0;
        int qx = qg - qyl * 40;
        float4 qv[8];
        {
            const float4* qsrc = reinterpret_cast<const float4*>(
                g_qp + (size_t)(nh_base + qy0 * WIM + qg) * HD);
#pragma unroll
            for (int u = 0; u < 8; u++) qv[u] = qsrc[u];
        }
        const float* relp = g_rel + (size_t)nh * WS2 * HW + qy0 * WIM + qg;
        int wy = 0, wx = wg;
#pragma unroll 1
        for (int w = wg; w < WS2; w += 8) {
            int ky = qy0 + qyl + wy - 7, kx = qx + wx - 7;
            bool img = ((unsigned)ky < HI) & ((unsigned)kx < WIM);
            const float4* k4 = reinterpret_cast<const float4*>(
                sK + ((qyl + wy) * PADW + qx + wx) * KP);
            float rel = __ldg(relp + (size_t)w * HW);
            float4 a = z4;
#pragma unroll
            for (int u = 0; u < 8; u++) {
                float4 kv = k4[u], qq = qv[u];
                a.x = fmaf(qq.x, kv.x, a.x);
                a.y = fmaf(qq.y, kv.y, a.y);
                a.z = fmaf(qq.z, kv.z, a.z);
                a.w = fmaf(qq.w, kv.w, a.w);
            }
            float qk = (a.x + a.y) + (a.z + a.w);
            sL[qg * LPQ + wy * 16 + wx] = (img ? qk : -NEGV) + rel;
            wx += 8;
            if (wx >= WSZ) { wx -= WSZ; wy++; }
        }
    }
    __syncthreads();

    // ---- V staging (pitch 32) + relv [d][w] -> sV [w][d] ----
    for (int i = tid; i < KROWS * 320; i += 640) {
        int r = i / 320, rem = i - r * 320;
        int ky = qy0 - 7 + r;
        float4 val = z4;
        if ((unsigned)ky < HI)
            val = reinterpret_cast<const float4*>(
                      g_vp + (size_t)(nh_base + ky * WIM) * HD)[rem];
        reinterpret_cast<float4*>(sK + (r * PADW + 7) * HD)[rem] = val;
    }
    for (int i = tid; i < KROWS * 112; i += 640) {    // V pad cols
        int r = i / 112, rem = i - r * 112;
        int c = rem >> 3, u = rem & 7;
        int col = (c < 7) ? c : (c + 40);
        *reinterpret_cast<float4*>(sK + (r * PADW + col) * HD + 4 * u) = z4;
    }
    {
        const float* rv = relv_g + (size_t)h * HD * WS2;
        for (int i = tid; i < HD * WS2; i += 640) {
            int d = i / WS2, w = i - d * WS2;
            sV[w * HD + d] = rv[i];
        }
        if (tid < HD) sV[WS2 * HD + tid] = 0.0f;      // ghost relv row
    }

    // ---- softmax: 20 warps x 4 queries over the padded 240-slot rows ----
    {
        int warp = tid >> 5, lane = tid & 31;
#pragma unroll 1
        for (int qq = 0; qq < 4; qq++) {
            int qg = warp * 4 + qq;
            float* Lp = sL + qg * LPQ;
            float vals[8];
            float m = -3.0e38f;
#pragma unroll
            for (int u = 0; u < 8; u++) {
                int slot = lane + u * 32;
                bool ok = (slot < LPQ) && ((slot & 15) != 15);
                vals[u] = ok ? Lp[slot] : -3.0e38f;
                m = fmaxf(m, vals[u]);
            }
#pragma unroll
            for (int off = 16; off > 0; off >>= 1)
                m = fmaxf(m, __shfl_xor_sync(0xffffffffu, m, off));
            float s = 0.0f;
#pragma unroll
            for (int u = 0; u < 8; u++) { float p = __expf(vals[u] - m); vals[u] = p; s += p; }
#pragma unroll
            for (int off = 16; off > 0; off >>= 1)
                s += __shfl_xor_sync(0xffffffffu, s, off);
            float inv = 1.0f / s;
            float* gp = p_out + (size_t)(nh_base + qy0 * WIM + qg) * WS2;
#pragma unroll
            for (int u = 0; u < 8; u++) {
                int slot = lane + u * 32;
                if (slot < LPQ) {
                    float p = vals[u] * inv;          // ghost slots -> exactly 0
                    Lp[slot] = p;
                    if ((slot & 15) != 15)
                        gp[slot - (slot >> 4)] = p;   // w = wy*15+wx
                }
            }
        }
    }
    __syncthreads();

    // ---- fused aggregation: warp = 4 consecutive qx (one row), lane = d ----
    {
        int warp = tid >> 5, lane = tid & 31;
        int qyl = (warp >= 10) ? 1 : 0;
        int qx0 = (warp - qyl * 10) * 4;              // 0..36
        int qbase = qyl * 40 + qx0;
        float av[4] = {0.f, 0.f, 0.f, 0.f};
        float ab[4] = {0.f, 0.f, 0.f, 0.f};
#pragma unroll 1
        for (int ky = 0; ky < WSZ; ky++) {
            const float* vrow = sK + ((qyl + ky) * PADW + qx0) * HD + lane;
            float vv[19];
#pragma unroll
            for (int c = 0; c < 19; c++) vv[c] = vrow[c * HD];
            const float* rvrow = sV + ky * WSZ * HD + lane;
            float rvv[16];
#pragma unroll
            for (int t = 0; t < 16; t++) rvv[t] = rvrow[t * HD];
#pragma unroll
            for (int j = 0; j < 4; j++) {
                const float* Lp = sL + (qbase + j) * LPQ + ky * 16;
#pragma unroll
                for (int g = 0; g < 4; g++) {
                    float4 p4 = *reinterpret_cast<const float4*>(Lp + g * 4);
                    float pe[4] = {p4.x, p4.y, p4.z, p4.w};
#pragma unroll
                    for (int t = 0; t < 4; t++) {
                        int wx = g * 4 + t;           // wx=15: p==0
                        av[j] = fmaf(pe[t], vv[j + wx], av[j]);
                        ab[j] = fmaf(pe[t], rvv[wx], ab[j]);
                    }
                }
            }
        }
#pragma unroll
        for (int j = 0; j < 4; j++) {
            int iy = (qy0 + qyl) * WIM + qx0 + j;
            g_ctx[((size_t)iy * NB + n) * CH + h * HD + lane] = av[j] + ab[j];
        }
    }
}

// ============================================================
// Kernel 4: output projection. 64x64 tile, 512 threads,
// 2x4 outputs/thread (16 warps/SM).
// ============================================================
__global__ void __launch_bounds__(512) outproj_kernel(
    const float* __restrict__ Wp, const float* __restrict__ bp,
    float* __restrict__ out)
{
    __shared__ __align__(16) float As[64][32];
    __shared__ __align__(16) float BsT[64][33];

    int r0 = blockIdx.y * 64, o0 = blockIdx.x * 64;
    int tid = threadIdx.x;
    int tx = tid & 15, ty = tid >> 4;     // ty 0..31 -> 2 rows each

    float acc[2][4] = {};

    for (int k0 = 0; k0 < CH; k0 += 32) {
#pragma unroll
        for (int s = 0; s < 4; s++) {
            int idx = tid + s * 512;
            int row = idx >> 5, col = idx & 31;
            As[row][col]  = g_ctx[(size_t)(r0 + row) * CH + k0 + col];
            BsT[row][col] = Wp[(size_t)(o0 + row) * CH + k0 + col];
        }
        __syncthreads();
#pragma unroll
        for (int cc = 0; cc < 32; cc++) {
            float aa[2], bb[4];
#pragma unroll
            for (int i = 0; i < 2; i++) aa[i] = As[ty * 2 + i][cc];
#pragma unroll
            for (int j = 0; j < 4; j++) bb[j] = BsT[tx * 4 + j][cc];
#pragma unroll
            for (int i = 0; i < 2; i++)
#pragma unroll
                for (int j = 0; j < 4; j++)
                    acc[i][j] = fmaf(aa[i], bb[j], acc[i][j]);
        }
        __syncthreads();
    }

#pragma unroll
    for (int i = 0; i < 2; i++) {
        int r = r0 + ty * 2 + i;
#pragma unroll
        for (int j = 0; j < 4; j++) {
            int o = o0 + tx * 4 + j;
            out[(size_t)r * CH + o] = acc[i][j] + bp[o];
        }
    }
}

// ============================================================
extern "C" void kernel_launch(void* const* d_in, const int* in_sizes, int n_in,
                              void* d_out, int out_size)
{
    const float* q    = (const float*)d_in[0];
    const float* k    = (const float*)d_in[1];
    const float* v    = (const float*)d_in[2];
    const float* Wq   = (const float*)d_in[3];
    const float* bq   = (const float*)d_in[4];
    const float* Wk   = (const float*)d_in[5];
    const float* bk   = (const float*)d_in[6];
    const float* Wv   = (const float*)d_in[7];
    const float* bv   = (const float*)d_in[8];
    const float* relw = (const float*)d_in[9];
    const float* relb = (const float*)d_in[10];
    const float* relv = (const float*)d_in[11];
    const float* Wp   = (const float*)d_in[12];
    const float* bp   = (const float*)d_in[13];
    (void)in_sizes; (void)n_in;

    float* out  = (float*)d_out;
    float* attn = (out_size >= OUT_ELEMS + ATTN_ELEMS) ? (out + OUT_ELEMS) : nullptr;

    static bool s_init = false;
    if (!s_init) {
        cudaFuncSetAttribute(attn_kernel,
                             cudaFuncAttributeMaxDynamicSharedMemorySize, SM_BYTES);
        s_init = true;
    }

    float* p_dst;
    cudaGetSymbolAddress((void**)&p_dst, g_pb);
    if (attn) p_dst = attn;

    proj_kernel<<<dim3(25, 2, 6), 512>>>(q, k, v, Wq, bq, Wk, bk, Wv, bv);
    relgemm_kernel<<<dim3(25, NHD, NB), 256>>>(relw, relb);
    attn_kernel<<<dim3(HI / GQ, NHD, NB), 640, SM_BYTES>>>(relv, p_dst);
    outproj_kernel<<<dim3(4, 50), 512>>>(Wp, bp, out);
}

// round 15
// speedup vs baseline: 1.0190x; 1.0190x over previous
#include <cuda_runtime.h>
#include <math.h>

#define NB   2
#define NHD  8
#define HD   32
#define CH   256
#define HI   40
#define WIM  40
#define HW   1600
#define WSZ  15
#define WS2  225
#define NEGV 1e8f
#define INV_T 0.17677669529663687f   // 1/sqrt(32)

#define OUT_ELEMS  (HW*NB*CH)            // 819200
#define ATTN_ELEMS (NB*NHD*HW*WS2)       // 5760000
#define RN         (HW*NB)               // 3200 rows of ctx

// ---- scratch ----
__device__ float g_qp[NB*NHD*HW*HD];     // [n][h][q][d] unscaled
__device__ float g_kp[NB*NHD*HW*HD];     // [n][h][j][d] scaled by 1/T
__device__ float g_vp[NB*NHD*HW*HD];
__device__ float g_ctx[CH*RN];           // TRANSPOSED: [c][i*NB+n]
__device__ float g_rel[NB*NHD*WS2*HW];   // [n][h][w][q]  rel logits
__device__ float g_pb[ATTN_ELEMS];       // fallback p storage
__device__ float g_WT[4*CH*CH];          // Wq^T, Wk^T, Wv^T, Wp^T  [c][o]

// ============================================================
// Kernel 0: transpose the four 256x256 weight matrices.
// grid (8,8,4), block (32,8).
// ============================================================
__global__ void __launch_bounds__(256) wtrans_kernel(
    const float* __restrict__ Wq, const float* __restrict__ Wk,
    const float* __restrict__ Wv, const float* __restrict__ Wp)
{
    __shared__ float t[32][33];
    const float* src;
    switch (blockIdx.z) {
        case 0: src = Wq; break;
        case 1: src = Wk; break;
        case 2: src = Wv; break;
        default: src = Wp; break;
    }
    float* dst = g_WT + (size_t)blockIdx.z * CH * CH;
    int x0 = blockIdx.x * 32, y0 = blockIdx.y * 32;
    int tx = threadIdx.x, ty = threadIdx.y;
#pragma unroll
    for (int j = ty; j < 32; j += 8)
        t[j][tx] = src[(size_t)(y0 + j) * CH + x0 + tx];
    __syncthreads();
#pragma unroll
    for (int j = ty; j < 32; j += 8)
        dst[(size_t)(x0 + j) * CH + y0 + tx] = t[tx][j];
}

// ============================================================
// Kernel 1: fused QKV projection. 128x64 tile, 256 threads, 8x4
// per thread. Weights staged k-major from g_WT (float4 aa loads).
// ============================================================
__global__ void __launch_bounds__(256) proj_kernel(
    const float* __restrict__ q, const float* __restrict__ k, const float* __restrict__ v,
    const float* __restrict__ bq, const float* __restrict__ bk,
    const float* __restrict__ bv)
{
    __shared__ __align__(16) float WsT[32 * 128];   // [cc][o]
    __shared__ __align__(16) float Bs[32][64];

    int z = blockIdx.z;
    int n = z & 1, t = z >> 1;
    const float* X; const float* b; float* Y; float scale;
    if (t == 0)      { X = q; b = bq; Y = g_qp; scale = 1.0f;  }
    else if (t == 1) { X = k; b = bk; Y = g_kp; scale = INV_T; }
    else             { X = v; b = bv; Y = g_vp; scale = 1.0f;  }
    X += (size_t)n * CH * HW;
    const float* WT = g_WT + (size_t)t * CH * CH;   // [c][o]

    int o0 = blockIdx.y * 128, p0 = blockIdx.x * 64;
    int tid = threadIdx.x;
    int tx = tid & 15, ty = tid >> 4;

    float acc[8][4] = {};

    for (int k0 = 0; k0 < CH; k0 += 32) {
#pragma unroll
        for (int s = 0; s < 16; s++) {
            int idx = tid + s * 256;
            int o = idx & 127, c = idx >> 7;
            WsT[c * 128 + o] = WT[(size_t)(k0 + c) * CH + o0 + o];
        }
#pragma unroll
        for (int s = 0; s < 8; s++) {
            int idx = tid + s * 256;
            int col = idx & 63, row = idx >> 6;
            Bs[row][col] = X[(size_t)(k0 + row) * HW + p0 + col];
        }
        __syncthreads();
#pragma unroll
        for (int cc = 0; cc < 32; cc++) {
            float4 b4 = *reinterpret_cast<const float4*>(&Bs[cc][tx * 4]);
            float bb[4] = {b4.x, b4.y, b4.z, b4.w};
            float4 a0 = *reinterpret_cast<const float4*>(&WsT[cc * 128 + ty * 8]);
            float4 a1 = *reinterpret_cast<const float4*>(&WsT[cc * 128 + ty * 8 + 4]);
            float aa[8] = {a0.x, a0.y, a0.z, a0.w, a1.x, a1.y, a1.z, a1.w};
#pragma unroll
            for (int i = 0; i < 8; i++)
#pragma unroll
                for (int j = 0; j < 4; j++)
                    acc[i][j] = fmaf(aa[i], bb[j], acc[i][j]);
        }
        __syncthreads();
    }

#pragma unroll
    for (int i = 0; i < 8; i++) {
        int o = o0 + ty * 8 + i;
        int h = o >> 5, d = o & 31;
        float bias = b[o];
#pragma unroll
        for (int j = 0; j < 4; j++) {
            int p = p0 + tx * 4 + j;
            float val = (acc[i][j] + bias) * scale;
            Y[((size_t)(n * NHD + h) * HW + p) * HD + d] = val;
        }
    }
}

// ============================================================
// Kernel 2: rel logits GEMM (unchanged).
// ============================================================
__global__ void __launch_bounds__(256) relgemm_kernel(
    const float* __restrict__ relw_g,   // [NHD][WS2][HD]
    const float* __restrict__ relb_g)   // [NHD][WS2]
{
    __shared__ __align__(16) float sW[WS2 * HD];   // [w][d]
    __shared__ float sb[WS2];

    int q0 = blockIdx.x * 64, h = blockIdx.y, n = blockIdx.z;
    int tid = threadIdx.x;
    int nh = n * NHD + h;

    {
        const float4* src = reinterpret_cast<const float4*>(relw_g + (size_t)h * WS2 * HD);
        float4* dst = reinterpret_cast<float4*>(sW);
        for (int i = tid; i < WS2 * HD / 4; i += 256) dst[i] = src[i];
        const float* bs = relb_g + (size_t)h * WS2;
        for (int i = tid; i < WS2; i += 256) sb[i] = bs[i];
    }
    __syncthreads();

    int qi = tid & 63, wg = tid >> 6;
    int qq = q0 + qi;
    float4 qv[8];
    {
        const float4* qsrc = reinterpret_cast<const float4*>(
            g_qp + (size_t)(nh * HW + qq) * HD);
#pragma unroll
        for (int u = 0; u < 8; u++) qv[u] = qsrc[u];
    }
    float* dst = g_rel + (size_t)nh * WS2 * HW + qq;
#pragma unroll 1
    for (int w = wg; w < WS2; w += 4) {
        const float4* r4 = reinterpret_cast<const float4*>(sW + w * HD);
        float4 a = make_float4(0.f, 0.f, 0.f, 0.f);
#pragma unroll
        for (int u = 0; u < 8; u++) {
            float4 rv = r4[u], qu = qv[u];
            a.x = fmaf(qu.x, rv.x, a.x);
            a.y = fmaf(qu.y, rv.y, a.y);
            a.z = fmaf(qu.z, rv.z, a.z);
            a.w = fmaf(qu.w, rv.w, a.w);
        }
        dst[(size_t)w * HW] = (a.x + a.y) + (a.z + a.w) + sb[w];
    }
}

// ============================================================
// Kernel 3: local attention (R12, except ctx written transposed).
// ============================================================
#define GQ    2
#define QG    80
#define KROWS 16
#define PADW  54
#define KP    36
#define LPQ   240
#define SM_K      0                          // 16*54*36 = 31104
#define SM_L      31104                      // 80*240   = 19200
#define SM_V      50304                      // 226*32   = 7232
#define SM_FLOATS 57536
#define SM_BYTES  (SM_FLOATS * 4)            // 230144 B

__global__ void __launch_bounds__(640, 1) attn_kernel(
    const float* __restrict__ relv_g,   // [NHD][HD][WS2]
    float* __restrict__ p_out)
{
    int qy0 = blockIdx.x * GQ, h = blockIdx.y, n = blockIdx.z;
    int tid = threadIdx.x;
    extern __shared__ __align__(16) float sm[];
    float* sK = sm + SM_K;
    float* sL = sm + SM_L;
    float* sV = sm + SM_V;

    int nh = n * NHD + h;
    int nh_base = nh * HW;
    const float4 z4 = make_float4(0.f, 0.f, 0.f, 0.f);

    // ---- stage K (16 rows, OOB rows -> 0) + pad cols ----
    for (int i = tid; i < KROWS * 320; i += 640) {
        int r = i / 320, rem = i - r * 320;
        int ky = qy0 - 7 + r;
        float4 val = z4;
        if ((unsigned)ky < HI)
            val = reinterpret_cast<const float4*>(
                      g_kp + (size_t)(nh_base + ky * WIM) * HD)[rem];
        int kx = rem >> 3, u = rem & 7;
        *reinterpret_cast<float4*>(sK + (r * PADW + 7 + kx) * KP + 4 * u) = val;
    }
    for (int i = tid; i < KROWS * 112; i += 640) {
        int r = i / 112, rem = i - r * 112;
        int c = rem >> 3, u = rem & 7;
        int col = (c < 7) ? c : (c + 40);             // pads: 0..6, 47..53
        *reinterpret_cast<float4*>(sK + (r * PADW + col) * KP + 4 * u) = z4;
    }
    __syncthreads();

    // ---- logits: thread = (qg = tid%80, wg = tid/80 in 0..7) ----
    {
        int qg = tid % QG;
        int wg = tid / QG;
        int qyl = (qg >= 40) ? 1 : 0;
        int qx = qg - qyl * 40;
        float4 qv[8];
        {
            const float4* qsrc = reinterpret_cast<const float4*>(
                g_qp + (size_t)(nh_base + qy0 * WIM + qg) * HD);
#pragma unroll
            for (int u = 0; u < 8; u++) qv[u] = qsrc[u];
        }
        const float* relp = g_rel + (size_t)nh * WS2 * HW + qy0 * WIM + qg;
        int wy = 0, wx = wg;
#pragma unroll 1
        for (int w = wg; w < WS2; w += 8) {
            int ky = qy0 + qyl + wy - 7, kx = qx + wx - 7;
            bool img = ((unsigned)ky < HI) & ((unsigned)kx < WIM);
            const float4* k4 = reinterpret_cast<const float4*>(
                sK + ((qyl + wy) * PADW + qx + wx) * KP);
            float rel = __ldg(relp + (size_t)w * HW);
            float4 a = z4;
#pragma unroll
            for (int u = 0; u < 8; u++) {
                float4 kv = k4[u], qq = qv[u];
                a.x = fmaf(qq.x, kv.x, a.x);
                a.y = fmaf(qq.y, kv.y, a.y);
                a.z = fmaf(qq.z, kv.z, a.z);
                a.w = fmaf(qq.w, kv.w, a.w);
            }
            float qk = (a.x + a.y) + (a.z + a.w);
            sL[qg * LPQ + wy * 16 + wx] = (img ? qk : -NEGV) + rel;
            wx += 8;
            if (wx >= WSZ) { wx -= WSZ; wy++; }
        }
    }
    __syncthreads();

    // ---- V staging (pitch 32) + relv [d][w] -> sV [w][d] ----
    for (int i = tid; i < KROWS * 320; i += 640) {
        int r = i / 320, rem = i - r * 320;
        int ky = qy0 - 7 + r;
        float4 val = z4;
        if ((unsigned)ky < HI)
            val = reinterpret_cast<const float4*>(
                      g_vp + (size_t)(nh_base + ky * WIM) * HD)[rem];
        reinterpret_cast<float4*>(sK + (r * PADW + 7) * HD)[rem] = val;
    }
    for (int i = tid; i < KROWS * 112; i += 640) {    // V pad cols
        int r = i / 112, rem = i - r * 112;
        int c = rem >> 3, u = rem & 7;
        int col = (c < 7) ? c : (c + 40);
        *reinterpret_cast<float4*>(sK + (r * PADW + col) * HD + 4 * u) = z4;
    }
    {
        const float* rv = relv_g + (size_t)h * HD * WS2;
        for (int i = tid; i < HD * WS2; i += 640) {
            int d = i / WS2, w = i - d * WS2;
            sV[w * HD + d] = rv[i];
        }
        if (tid < HD) sV[WS2 * HD + tid] = 0.0f;      // ghost relv row
    }

    // ---- softmax: 20 warps x 4 queries over the padded 240-slot rows ----
    {
        int warp = tid >> 5, lane = tid & 31;
#pragma unroll 1
        for (int qq = 0; qq < 4; qq++) {
            int qg = warp * 4 + qq;
            float* Lp = sL + qg * LPQ;
            float vals[8];
            float m = -3.0e38f;
#pragma unroll
            for (int u = 0; u < 8; u++) {
                int slot = lane + u * 32;
                bool ok = (slot < LPQ) && ((slot & 15) != 15);
                vals[u] = ok ? Lp[slot] : -3.0e38f;
                m = fmaxf(m, vals[u]);
            }
#pragma unroll
            for (int off = 16; off > 0; off >>= 1)
                m = fmaxf(m, __shfl_xor_sync(0xffffffffu, m, off));
            float s = 0.0f;
#pragma unroll
            for (int u = 0; u < 8; u++) { float p = __expf(vals[u] - m); vals[u] = p; s += p; }
#pragma unroll
            for (int off = 16; off > 0; off >>= 1)
                s += __shfl_xor_sync(0xffffffffu, s, off);
            float inv = 1.0f / s;
            float* gp = p_out + (size_t)(nh_base + qy0 * WIM + qg) * WS2;
#pragma unroll
            for (int u = 0; u < 8; u++) {
                int slot = lane + u * 32;
                if (slot < LPQ) {
                    float p = vals[u] * inv;          // ghost slots -> exactly 0
                    Lp[slot] = p;
                    if ((slot & 15) != 15)
                        gp[slot - (slot >> 4)] = p;   // w = wy*15+wx
                }
            }
        }
    }
    __syncthreads();

    // ---- fused aggregation: warp = 4 consecutive qx (one row), lane = d ----
    {
        int warp = tid >> 5, lane = tid & 31;
        int qyl = (warp >= 10) ? 1 : 0;
        int qx0 = (warp - qyl * 10) * 4;              // 0..36
        int qbase = qyl * 40 + qx0;
        float av[4] = {0.f, 0.f, 0.f, 0.f};
        float ab[4] = {0.f, 0.f, 0.f, 0.f};
#pragma unroll 1
        for (int ky = 0; ky < WSZ; ky++) {
            const float* vrow = sK + ((qyl + ky) * PADW + qx0) * HD + lane;
            float vv[19];
#pragma unroll
            for (int c = 0; c < 19; c++) vv[c] = vrow[c * HD];
            const float* rvrow = sV + ky * WSZ * HD + lane;
            float rvv[16];
#pragma unroll
            for (int t = 0; t < 16; t++) rvv[t] = rvrow[t * HD];
#pragma unroll
            for (int j = 0; j < 4; j++) {
                const float* Lp = sL + (qbase + j) * LPQ + ky * 16;
#pragma unroll
                for (int g = 0; g < 4; g++) {
                    float4 p4 = *reinterpret_cast<const float4*>(Lp + g * 4);
                    float pe[4] = {p4.x, p4.y, p4.z, p4.w};
#pragma unroll
                    for (int t = 0; t < 4; t++) {
                        int wx = g * 4 + t;           // wx=15: p==0
                        av[j] = fmaf(pe[t], vv[j + wx], av[j]);
                        ab[j] = fmaf(pe[t], rvv[wx], ab[j]);
                    }
                }
            }
        }
        // ctx is TRANSPOSED: [c][i*NB+n]
#pragma unroll
        for (int j = 0; j < 4; j++) {
            int iy = (qy0 + qyl) * WIM + qx0 + j;
            g_ctx[(size_t)(h * HD + lane) * RN + iy * NB + n] = av[j] + ab[j];
        }
    }
}

// ============================================================
// Kernel 4: output projection. 64x64 tile, 256 threads, 4x4 per
// thread; BOTH operands staged k-major -> 2 float4 LDS / 16 FMA.
// ============================================================
__global__ void __launch_bounds__(256) outproj_kernel(
    const float* __restrict__ bp, float* __restrict__ out)
{
    __shared__ __align__(16) float AsT[32 * 68];   // [cc][r]
    __shared__ __align__(16) float WsT[32 * 68];   // [cc][o]

    int r0 = blockIdx.y * 64, o0 = blockIdx.x * 64;
    int tid = threadIdx.x;
    int tx = tid & 15, ty = tid >> 4;
    const float* WT = g_WT + (size_t)3 * CH * CH;  // Wp^T [c][o]

    float acc[4][4] = {};

    for (int k0 = 0; k0 < CH; k0 += 32) {
#pragma unroll
        for (int s = 0; s < 8; s++) {
            int idx = tid + s * 256;
            int r = idx & 63, c = idx >> 6;
            AsT[c * 68 + r] = g_ctx[(size_t)(k0 + c) * RN + r0 + r];
            WsT[c * 68 + r] = WT[(size_t)(k0 + c) * CH + o0 + r];
        }
        __syncthreads();
#pragma unroll
        for (int cc = 0; cc < 32; cc++) {
            float4 a4 = *reinterpret_cast<const float4*>(&AsT[cc * 68 + ty * 4]);
            float4 b4 = *reinterpret_cast<const float4*>(&WsT[cc * 68 + tx * 4]);
            float aa[4] = {a4.x, a4.y, a4.z, a4.w};
            float bb[4] = {b4.x, b4.y, b4.z, b4.w};
#pragma unroll
            for (int i = 0; i < 4; i++)
#pragma unroll
                for (int j = 0; j < 4; j++)
                    acc[i][j] = fmaf(aa[i], bb[j], acc[i][j]);
        }
        __syncthreads();
    }

#pragma unroll
    for (int i = 0; i < 4; i++) {
        int r = r0 + ty * 4 + i;
#pragma unroll
        for (int j = 0; j < 4; j++) {
            int o = o0 + tx * 4 + j;
            out[(size_t)r * CH + o] = acc[i][j] + bp[o];
        }
    }
}

// ============================================================
extern "C" void kernel_launch(void* const* d_in, const int* in_sizes, int n_in,
                              void* d_out, int out_size)
{
    const float* q    = (const float*)d_in[0];
    const float* k    = (const float*)d_in[1];
    const float* v    = (const float*)d_in[2];
    const float* Wq   = (const float*)d_in[3];
    const float* bq   = (const float*)d_in[4];
    const float* Wk   = (const float*)d_in[5];
    const float* bk   = (const float*)d_in[6];
    const float* Wv   = (const float*)d_in[7];
    const float* bv   = (const float*)d_in[8];
    const float* relw = (const float*)d_in[9];
    const float* relb = (const float*)d_in[10];
    const float* relv = (const float*)d_in[11];
    const float* Wp   = (const float*)d_in[12];
    const float* bp   = (const float*)d_in[13];
    (void)in_sizes; (void)n_in; (void)Wp;

    float* out  = (float*)d_out;
    float* attn = (out_size >= OUT_ELEMS + ATTN_ELEMS) ? (out + OUT_ELEMS) : nullptr;

    static bool s_init = false;
    if (!s_init) {
        cudaFuncSetAttribute(attn_kernel,
                             cudaFuncAttributeMaxDynamicSharedMemorySize, SM_BYTES);
        s_init = true;
    }

    float* p_dst;
    cudaGetSymbolAddress((void**)&p_dst, g_pb);
    if (attn) p_dst = attn;

    wtrans_kernel<<<dim3(8, 8, 4), dim3(32, 8)>>>(Wq, Wk, Wv, Wp);
    proj_kernel<<<dim3(25, 2, 6), 256>>>(q, k, v, bq, bk, bv);
    relgemm_kernel<<<dim3(25, NHD, NB), 256>>>(relw, relb);
    attn_kernel<<<dim3(HI / GQ, NHD, NB), 640, SM_BYTES>>>(relv, p_dst);
    outproj_kernel<<<dim3(4, 50), 256>>>(bp, out);
}

// round 17
// speedup vs baseline: 1.0728x; 1.0528x over previous
#include <cuda_runtime.h>
#include <math.h>

#define NB   2
#define NHD  8
#define HD   32
#define CH   256
#define HI   40
#define WIM  40
#define HW   1600
#define WSZ  15
#define WS2  225
#define NEGV 1e8f
#define INV_T 0.17677669529663687f   // 1/sqrt(32)

#define OUT_ELEMS  (HW*NB*CH)            // 819200
#define ATTN_ELEMS (NB*NHD*HW*WS2)       // 5760000

// ---- scratch ----
__device__ float g_qp[NB*NHD*HW*HD];     // [n][h][q][d] unscaled
__device__ float g_kp[NB*NHD*HW*HD];     // [n][h][j][d] scaled by 1/T
__device__ float g_vp[NB*NHD*HW*HD];
__device__ float g_ctx[HW*NB*CH];        // [i][n][c]
__device__ float g_rel[NB*NHD*WS2*HW];   // [n][h][w][q]  rel logits
__device__ float g_pb[ATTN_ELEMS];       // fallback p storage

// ============================================================
// Kernel 1: fused QKV projection (R12 version).
// ============================================================
__global__ void __launch_bounds__(256, 2) proj_kernel(
    const float* __restrict__ q, const float* __restrict__ k, const float* __restrict__ v,
    const float* __restrict__ Wq, const float* __restrict__ bq,
    const float* __restrict__ Wk, const float* __restrict__ bk,
    const float* __restrict__ Wv, const float* __restrict__ bv)
{
    __shared__ __align__(16) float Ws[128 * 33];
    __shared__ __align__(16) float Bs[32][64];

    int z = blockIdx.z;
    int n = z & 1, t = z >> 1;
    const float* X; const float* W; const float* b; float* Y; float scale;
    if (t == 0)      { X = q; W = Wq; b = bq; Y = g_qp; scale = 1.0f;  }
    else if (t == 1) { X = k; W = Wk; b = bk; Y = g_kp; scale = INV_T; }
    else             { X = v; W = Wv; b = bv; Y = g_vp; scale = 1.0f;  }
    X += (size_t)n * CH * HW;

    int o0 = blockIdx.y * 128, p0 = blockIdx.x * 64;
    int tid = threadIdx.x;
    int tx = tid & 15, ty = tid >> 4;

    float acc[8][4] = {};

    for (int k0 = 0; k0 < CH; k0 += 32) {
#pragma unroll
        for (int s = 0; s < 16; s++) {
            int idx = tid + s * 256;
            int row = idx >> 5, col = idx & 31;
            Ws[row * 33 + col] = W[(size_t)(o0 + row) * CH + k0 + col];
        }
#pragma unroll
        for (int s = 0; s < 8; s++) {
            int idx = tid + s * 256;
            int col = idx & 63, row = idx >> 6;
            Bs[row][col] = X[(size_t)(k0 + row) * HW + p0 + col];
        }
        __syncthreads();
#pragma unroll
        for (int cc = 0; cc < 32; cc++) {
            float4 b4 = *reinterpret_cast<const float4*>(&Bs[cc][tx * 4]);
            float bb[4] = {b4.x, b4.y, b4.z, b4.w};
            float aa[8];
#pragma unroll
            for (int i = 0; i < 8; i++) aa[i] = Ws[(ty * 8 + i) * 33 + cc];
#pragma unroll
            for (int i = 0; i < 8; i++)
#pragma unroll
                for (int j = 0; j < 4; j++)
                    acc[i][j] = fmaf(aa[i], bb[j], acc[i][j]);
        }
        __syncthreads();
    }

#pragma unroll
    for (int i = 0; i < 8; i++) {
        int o = o0 + ty * 8 + i;
        int h = o >> 5, d = o & 31;
        float bias = b[o];
#pragma unroll
        for (int j = 0; j < 4; j++) {
            int p = p0 + tx * 4 + j;
            float val = (acc[i][j] + bias) * scale;
            Y[((size_t)(n * NHD + h) * HW + p) * HD + d] = val;
        }
    }
}

// ============================================================
// Kernel 2: rel logits GEMM (unchanged).
// ============================================================
__global__ void __launch_bounds__(256) relgemm_kernel(
    const float* __restrict__ relw_g,   // [NHD][WS2][HD]
    const float* __restrict__ relb_g)   // [NHD][WS2]
{
    __shared__ __align__(16) float sW[WS2 * HD];   // [w][d]
    __shared__ float sb[WS2];

    int q0 = blockIdx.x * 64, h = blockIdx.y, n = blockIdx.z;
    int tid = threadIdx.x;
    int nh = n * NHD + h;

    {
        const float4* src = reinterpret_cast<const float4*>(relw_g + (size_t)h * WS2 * HD);
        float4* dst = reinterpret_cast<float4*>(sW);
        for (int i = tid; i < WS2 * HD / 4; i += 256) dst[i] = src[i];
        const float* bs = relb_g + (size_t)h * WS2;
        for (int i = tid; i < WS2; i += 256) sb[i] = bs[i];
    }
    __syncthreads();

    int qi = tid & 63, wg = tid >> 6;
    int qq = q0 + qi;
    float4 qv[8];
    {
        const float4* qsrc = reinterpret_cast<const float4*>(
            g_qp + (size_t)(nh * HW + qq) * HD);
#pragma unroll
        for (int u = 0; u < 8; u++) qv[u] = qsrc[u];
    }
    float* dst = g_rel + (size_t)nh * WS2 * HW + qq;
#pragma unroll 1
    for (int w = wg; w < WS2; w += 4) {
        const float4* r4 = reinterpret_cast<const float4*>(sW + w * HD);
        float4 a = make_float4(0.f, 0.f, 0.f, 0.f);
#pragma unroll
        for (int u = 0; u < 8; u++) {
            float4 rv = r4[u], qu = qv[u];
            a.x = fmaf(qu.x, rv.x, a.x);
            a.y = fmaf(qu.y, rv.y, a.y);
            a.z = fmaf(qu.z, rv.z, a.z);
            a.w = fmaf(qu.w, rv.w, a.w);
        }
        dst[(size_t)w * HW] = (a.x + a.y) + (a.z + a.w) + sb[w];
    }
}

// ============================================================
// Kernel 3: local attention. Block per (qy pair, h, n). 640 thr.
// LPQ=244 pitch (4-way instead of 16-way STS conflicts); data
// slots 0..239 (15 wy x 16, wx=15 ghost -> p=0). rel logits are
// bulk-prefetched into sL during K staging (coalesced, MLP-high),
// removing the per-window dependent DRAM LDG from the hot loop.
// ============================================================
#define GQ    2
#define QG    80
#define KROWS 16
#define PADW  54
#define KP    36
#define LPQ   244                            // pitch (mult of 4; 4-way banks)
#define SLOTS 240                            // data region per query
#define SM_K      0                          // 16*54*36 = 31104
#define SM_L      31104                      // 80*244   = 19520
#define SM_V      50624                      // 226*32   = 7232
#define SM_FLOATS 57856
#define SM_BYTES  (SM_FLOATS * 4)            // 231424 B (<= 232448)

__global__ void __launch_bounds__(640, 1) attn_kernel(
    const float* __restrict__ relv_g,   // [NHD][HD][WS2]
    float* __restrict__ p_out)
{
    int qy0 = blockIdx.x * GQ, h = blockIdx.y, n = blockIdx.z;
    int tid = threadIdx.x;
    extern __shared__ __align__(16) float sm[];
    float* sK = sm + SM_K;
    float* sL = sm + SM_L;
    float* sV = sm + SM_V;

    int nh = n * NHD + h;
    int nh_base = nh * HW;
    const float4 z4 = make_float4(0.f, 0.f, 0.f, 0.f);

    // ---- stage K (16 rows, OOB rows -> 0) + pad cols + rel prefetch ----
    for (int i = tid; i < KROWS * 320; i += 640) {
        int r = i / 320, rem = i - r * 320;
        int ky = qy0 - 7 + r;
        float4 val = z4;
        if ((unsigned)ky < HI)
            val = reinterpret_cast<const float4*>(
                      g_kp + (size_t)(nh_base + ky * WIM) * HD)[rem];
        int kx = rem >> 3, u = rem & 7;
        *reinterpret_cast<float4*>(sK + (r * PADW + 7 + kx) * KP + 4 * u) = val;
    }
    for (int i = tid; i < KROWS * 112; i += 640) {
        int r = i / 112, rem = i - r * 112;
        int c = rem >> 3, u = rem & 7;
        int col = (c < 7) ? c : (c + 40);             // pads: 0..6, 47..53
        *reinterpret_cast<float4*>(sK + (r * PADW + col) * KP + 4 * u) = z4;
    }
    {   // bulk rel -> sL (coalesced over qg; independent loads, MLP ~28)
        const float* relsrc = g_rel + (size_t)nh * WS2 * HW + qy0 * WIM;
        for (int i = tid; i < WS2 * QG; i += 640) {
            int w = i / QG, qg = i - w * QG;
            int wy = w / WSZ, wx = w - wy * WSZ;
            sL[qg * LPQ + wy * 16 + wx] = relsrc[(size_t)w * HW + qg];
        }
    }
    __syncthreads();

    // ---- logits: thread = (qg = tid%80, wg = tid/80 in 0..7) ----
    {
        int qg = tid % QG;
        int wg = tid / QG;
        int qyl = (qg >= 40) ? 1 : 0;
        int qx = qg - qyl * 40;
        float4 qv[8];
        {
            const float4* qsrc = reinterpret_cast<const float4*>(
                g_qp + (size_t)(nh_base + qy0 * WIM + qg) * HD);
#pragma unroll
            for (int u = 0; u < 8; u++) qv[u] = qsrc[u];
        }
        int wy = 0, wx = wg;
#pragma unroll 1
        for (int w = wg; w < WS2; w += 8) {
            int slot = qg * LPQ + wy * 16 + wx;
            float rel = sL[slot];                     // prefetched rel logit
            int ky = qy0 + qyl + wy - 7, kx = qx + wx - 7;
            bool img = ((unsigned)ky < HI) & ((unsigned)kx < WIM);
            const float4* k4 = reinterpret_cast<const float4*>(
                sK + ((qyl + wy) * PADW + qx + wx) * KP);
            float4 a = z4;
#pragma unroll
            for (int u = 0; u < 8; u++) {
                float4 kv = k4[u], qq = qv[u];
                a.x = fmaf(qq.x, kv.x, a.x);
                a.y = fmaf(qq.y, kv.y, a.y);
                a.z = fmaf(qq.z, kv.z, a.z);
                a.w = fmaf(qq.w, kv.w, a.w);
            }
            float qk = (a.x + a.y) + (a.z + a.w);
            sL[slot] = (img ? qk : -NEGV) + rel;
            wx += 8;
            if (wx >= WSZ) { wx -= WSZ; wy++; }
        }
    }
    __syncthreads();

    // ---- V staging (pitch 32) + relv [d][w] -> sV [w][d] ----
    for (int i = tid; i < KROWS * 320; i += 640) {
        int r = i / 320, rem = i - r * 320;
        int ky = qy0 - 7 + r;
        float4 val = z4;
        if ((unsigned)ky < HI)
            val = reinterpret_cast<const float4*>(
                      g_vp + (size_t)(nh_base + ky * WIM) * HD)[rem];
        reinterpret_cast<float4*>(sK + (r * PADW + 7) * HD)[rem] = val;
    }
    for (int i = tid; i < KROWS * 112; i += 640) {    // V pad cols
        int r = i / 112, rem = i - r * 112;
        int c = rem >> 3, u = rem & 7;
        int col = (c < 7) ? c : (c + 40);
        *reinterpret_cast<float4*>(sK + (r * PADW + col) * HD + 4 * u) = z4;
    }
    {
        const float* rv = relv_g + (size_t)h * HD * WS2;
        for (int i = tid; i < HD * WS2; i += 640) {
            int d = i / WS2, w = i - d * WS2;
            sV[w * HD + d] = rv[i];
        }
        if (tid < HD) sV[WS2 * HD + tid] = 0.0f;      // ghost relv row
    }

    // ---- softmax: 20 warps x 4 queries over slots 0..239 ----
    {
        int warp = tid >> 5, lane = tid & 31;
#pragma unroll 1
        for (int qq = 0; qq < 4; qq++) {
            int qg = warp * 4 + qq;
            float* Lp = sL + qg * LPQ;
            float vals[8];
            float m = -3.0e38f;
#pragma unroll
            for (int u = 0; u < 8; u++) {
                int slot = lane + u * 32;
                bool ok = (slot < SLOTS) && ((slot & 15) != 15);
                vals[u] = ok ? Lp[slot] : -3.0e38f;
                m = fmaxf(m, vals[u]);
            }
#pragma unroll
            for (int off = 16; off > 0; off >>= 1)
                m = fmaxf(m, __shfl_xor_sync(0xffffffffu, m, off));
            float s = 0.0f;
#pragma unroll
            for (int u = 0; u < 8; u++) { float p = __expf(vals[u] - m); vals[u] = p; s += p; }
#pragma unroll
            for (int off = 16; off > 0; off >>= 1)
                s += __shfl_xor_sync(0xffffffffu, s, off);
            float inv = 1.0f / s;
            float* gp = p_out + (size_t)(nh_base + qy0 * WIM + qg) * WS2;
#pragma unroll
            for (int u = 0; u < 8; u++) {
                int slot = lane + u * 32;
                if (slot < SLOTS) {
                    float p = vals[u] * inv;          // ghost slots -> exactly 0
                    Lp[slot] = p;
                    if ((slot & 15) != 15)
                        gp[slot - (slot >> 4)] = p;   // w = wy*15+wx
                }
            }
        }
    }
    __syncthreads();

    // ---- fused aggregation: warp = 4 consecutive qx (one row), lane = d ----
    {
        int warp = tid >> 5, lane = tid & 31;
        int qyl = (warp >= 10) ? 1 : 0;
        int qx0 = (warp - qyl * 10) * 4;              // 0..36
        int qbase = qyl * 40 + qx0;
        float av[4] = {0.f, 0.f, 0.f, 0.f};
        float ab[4] = {0.f, 0.f, 0.f, 0.f};
#pragma unroll 1
        for (int ky = 0; ky < WSZ; ky++) {
            const float* vrow = sK + ((qyl + ky) * PADW + qx0) * HD + lane;
            float vv[19];
#pragma unroll
            for (int c = 0; c < 19; c++) vv[c] = vrow[c * HD];
            const float* rvrow = sV + ky * WSZ * HD + lane;
            float rvv[16];
#pragma unroll
            for (int t = 0; t < 16; t++) rvv[t] = rvrow[t * HD];
#pragma unroll
            for (int j = 0; j < 4; j++) {
                const float* Lp = sL + (qbase + j) * LPQ + ky * 16;
#pragma unroll
                for (int g = 0; g < 4; g++) {
                    float4 p4 = *reinterpret_cast<const float4*>(Lp + g * 4);
                    float pe[4] = {p4.x, p4.y, p4.z, p4.w};
#pragma unroll
                    for (int t = 0; t < 4; t++) {
                        int wx = g * 4 + t;           // wx=15: p==0
                        av[j] = fmaf(pe[t], vv[j + wx], av[j]);
                        ab[j] = fmaf(pe[t], rvv[wx], ab[j]);
                    }
                }
            }
        }
#pragma unroll
        for (int j = 0; j < 4; j++) {
            int iy = (qy0 + qyl) * WIM + qx0 + j;
            g_ctx[((size_t)iy * NB + n) * CH + h * HD + lane] = av[j] + ab[j];
        }
    }
}

// ============================================================
// Kernel 4: output projection (R12 version).
// ============================================================
__global__ void __launch_bounds__(256) outproj_kernel(
    const float* __restrict__ Wp, const float* __restrict__ bp,
    float* __restrict__ out)
{
    __shared__ __align__(16) float As[64][32];
    __shared__ __align__(16) float BsT[64][33];

    int r0 = blockIdx.y * 64, o0 = blockIdx.x * 64;
    int tid = threadIdx.x;
    int tx = tid & 15, ty = tid >> 4;

    float acc[4][4] = {};

    for (int k0 = 0; k0 < CH; k0 += 32) {
#pragma unroll
        for (int s = 0; s < 8; s++) {
            int idx = tid + s * 256;
            int row = idx >> 5, col = idx & 31;
            As[row][col]  = g_ctx[(size_t)(r0 + row) * CH + k0 + col];
            BsT[row][col] = Wp[(size_t)(o0 + row) * CH + k0 + col];
        }
        __syncthreads();
#pragma unroll
        for (int cc = 0; cc < 32; cc++) {
            float aa[4], bb[4];
#pragma unroll
            for (int i = 0; i < 4; i++) aa[i] = As[ty * 4 + i][cc];
#pragma unroll
            for (int j = 0; j < 4; j++) bb[j] = BsT[tx * 4 + j][cc];
#pragma unroll
            for (int i = 0; i < 4; i++)
#pragma unroll
                for (int j = 0; j < 4; j++)
                    acc[i][j] = fmaf(aa[i], bb[j], acc[i][j]);
        }
        __syncthreads();
    }

#pragma unroll
    for (int i = 0; i < 4; i++) {
        int r = r0 + ty * 4 + i;
#pragma unroll
        for (int j = 0; j < 4; j++) {
            int o = o0 + tx * 4 + j;
            out[(size_t)r * CH + o] = acc[i][j] + bp[o];
        }
    }
}

// ============================================================
extern "C" void kernel_launch(void* const* d_in, const int* in_sizes, int n_in,
                              void* d_out, int out_size)
{
    const float* q    = (const float*)d_in[0];
    const float* k    = (const float*)d_in[1];
    const float* v    = (const float*)d_in[2];
    const float* Wq   = (const float*)d_in[3];
    const float* bq   = (const float*)d_in[4];
    const float* Wk   = (const float*)d_in[5];
    const float* bk   = (const float*)d_in[6];
    const float* Wv   = (const float*)d_in[7];
    const float* bv   = (const float*)d_in[8];
    const float* relw = (const float*)d_in[9];
    const float* relb = (const float*)d_in[10];
    const float* relv = (const float*)d_in[11];
    const float* Wp   = (const float*)d_in[12];
    const float* bp   = (const float*)d_in[13];
    (void)in_sizes; (void)n_in;

    float* out  = (float*)d_out;
    float* attn = (out_size >= OUT_ELEMS + ATTN_ELEMS) ? (out + OUT_ELEMS) : nullptr;

    static bool s_init = false;
    if (!s_init) {
        cudaFuncSetAttribute(attn_kernel,
                             cudaFuncAttributeMaxDynamicSharedMemorySize, SM_BYTES);
        s_init = true;
    }

    float* p_dst;
    cudaGetSymbolAddress((void**)&p_dst, g_pb);
    if (attn) p_dst = attn;

    proj_kernel<<<dim3(25, 2, 6), 256>>>(q, k, v, Wq, bq, Wk, bk, Wv, bv);
    relgemm_kernel<<<dim3(25, NHD, NB), 256>>>(relw, relb);
    attn_kernel<<<dim3(HI / GQ, NHD, NB), 640, SM_BYTES>>>(relv, p_dst);
    outproj_kernel<<<dim3(4, 50), 256>>>(Wp, bp, out);
}